// round 1
// baseline (speedup 1.0000x reference)
#include <cuda_runtime.h>
#include <math.h>

#define D 1024
#define F 4096
#define MTOT 8192   // 4 * 2048

// ---- scratch (static device globals: allocation-free) ----
__device__ float g_Weff_fc[(size_t)F * D];     // 16 MB
__device__ float g_Weff_proj[(size_t)D * F];   // 16 MB
__device__ float g_H[(size_t)MTOT * F];        // 128 MB
__device__ unsigned int g_max2[2];

// ---------------------------------------------------------------------------
__global__ void k_init_max() { g_max2[0] = 0u; g_max2[1] = 0u; }

__global__ void k_absmax(const float* __restrict__ W, int n, int sel) {
    float m = 0.f;
    int stride = gridDim.x * blockDim.x;
    for (int i = blockIdx.x * blockDim.x + threadIdx.x; i < n; i += stride)
        m = fmaxf(m, fabsf(W[i]));
    #pragma unroll
    for (int o = 16; o; o >>= 1)
        m = fmaxf(m, __shfl_xor_sync(0xffffffffu, m, o));
    __shared__ float sm[8];
    int lane = threadIdx.x & 31, w = threadIdx.x >> 5;
    if (lane == 0) sm[w] = m;
    __syncthreads();
    if (threadIdx.x == 0) {
        float mm = sm[0];
        for (int i = 1; i < 8; i++) mm = fmaxf(mm, sm[i]);
        // all values >= 0 -> uint compare == float compare
        atomicMax(&g_max2[sel], __float_as_uint(mm));
    }
}

// W_eff[o,i] = fakequant(W[o,i]) + 2.0 * sum_r B[o,r] * A[r,i]
__global__ void k_build_weff(const float* __restrict__ W,
                             const float* __restrict__ A,
                             const float* __restrict__ Bm,
                             float* __restrict__ Weff,
                             int IN, int sel) {
    int o = blockIdx.y;
    int i = blockIdx.x * blockDim.x + threadIdx.x;
    __shared__ float Bs[16];
    if (threadIdx.x < 16) Bs[threadIdx.x] = Bm[o * 16 + threadIdx.x];
    __syncthreads();
    float scale = __uint_as_float(g_max2[sel]) * (1.0f / 127.0f);
    float w = W[(size_t)o * IN + i];
    float q = rintf(w / scale);               // jnp.round = half-to-even = rintf
    q = fminf(fmaxf(q, -128.0f), 127.0f);
    float wq = q * scale;
    float acc = 0.f;
    #pragma unroll
    for (int r = 0; r < 16; r++) acc = fmaf(Bs[r], A[(size_t)r * IN + i], acc);
    Weff[(size_t)o * IN + i] = wq + 2.0f * acc;
}

// ---------------------------------------------------------------------------
// C[m,n] = sum_k A[m,k] * B[n,k] + bias[n]   (both operands K-contiguous)
// 128x128 tile, BK=8, 256 threads, 8x8 accum per thread, register prefetch.
template <int GELU>
__global__ __launch_bounds__(256) void k_gemm(const float* __restrict__ A,
                                              const float* __restrict__ B,
                                              const float* __restrict__ bias,
                                              float* __restrict__ C,
                                              int M, int N, int K) {
    __shared__ float As[8][128];
    __shared__ float Bs[8][128];
    int t  = threadIdx.x;
    int tx = t & 15;          // 0..15 -> n sub-tile
    int ty = t >> 4;          // 0..15 -> m sub-tile
    int m0 = blockIdx.y * 128;
    int n0 = blockIdx.x * 128;

    int lr = t >> 1;          // 0..127: row within tile being loaded
    int lc = (t & 1) * 4;     // 0 or 4: k-offset of float4

    const float* Ag = A + (size_t)(m0 + lr) * K + lc;
    const float* Bg = B + (size_t)(n0 + lr) * K + lc;

    float acc[8][8];
    #pragma unroll
    for (int i = 0; i < 8; i++)
        #pragma unroll
        for (int j = 0; j < 8; j++) acc[i][j] = 0.f;

    float4 pa = *(const float4*)Ag;
    float4 pb = *(const float4*)Bg;

    for (int k0 = 0; k0 < K; k0 += 8) {
        As[lc + 0][lr] = pa.x; As[lc + 1][lr] = pa.y;
        As[lc + 2][lr] = pa.z; As[lc + 3][lr] = pa.w;
        Bs[lc + 0][lr] = pb.x; Bs[lc + 1][lr] = pb.y;
        Bs[lc + 2][lr] = pb.z; Bs[lc + 3][lr] = pb.w;
        __syncthreads();

        if (k0 + 8 < K) {                        // prefetch next slab
            pa = *(const float4*)(Ag + k0 + 8);
            pb = *(const float4*)(Bg + k0 + 8);
        }

        #pragma unroll
        for (int k = 0; k < 8; k++) {
            float ra[8], rb[8];
            #pragma unroll
            for (int j = 0; j < 8; j++) ra[j] = As[k][ty * 8 + j];
            #pragma unroll
            for (int j = 0; j < 8; j++) rb[j] = Bs[k][tx * 8 + j];
            #pragma unroll
            for (int i = 0; i < 8; i++)
                #pragma unroll
                for (int j = 0; j < 8; j++)
                    acc[i][j] = fmaf(ra[i], rb[j], acc[i][j]);
        }
        __syncthreads();
    }

    #pragma unroll
    for (int i = 0; i < 8; i++) {
        int m = m0 + ty * 8 + i;
        #pragma unroll
        for (int j = 0; j < 8; j++) {
            int n = n0 + tx * 8 + j;
            float v = acc[i][j] + bias[n];
            if (GELU) v = 0.5f * v * (1.0f + erff(v * 0.70710678118654752f));
            C[(size_t)m * N + n] = v;
        }
    }
}

// ---------------------------------------------------------------------------
extern "C" void kernel_launch(void* const* d_in, const int* in_sizes, int n_in,
                              void* d_out, int out_size) {
    const float* x      = (const float*)d_in[0];
    const float* W_fc   = (const float*)d_in[1];
    const float* b_fc   = (const float*)d_in[2];
    const float* A_fc   = (const float*)d_in[3];
    const float* B_fc   = (const float*)d_in[4];
    const float* W_proj = (const float*)d_in[5];
    const float* b_proj = (const float*)d_in[6];
    const float* A_proj = (const float*)d_in[7];
    const float* B_proj = (const float*)d_in[8];
    float* out = (float*)d_out;

    float *weff_fc, *weff_proj, *H;
    cudaGetSymbolAddress((void**)&weff_fc,   g_Weff_fc);
    cudaGetSymbolAddress((void**)&weff_proj, g_Weff_proj);
    cudaGetSymbolAddress((void**)&H,         g_H);

    k_init_max<<<1, 32>>>();
    k_absmax<<<256, 256>>>(W_fc,   F * D, 0);
    k_absmax<<<256, 256>>>(W_proj, D * F, 1);

    k_build_weff<<<dim3(D / 256, F), 256>>>(W_fc,   A_fc,   B_fc,   weff_fc,   D, 0);
    k_build_weff<<<dim3(F / 256, D), 256>>>(W_proj, A_proj, B_proj, weff_proj, F, 1);

    // GEMM1 + bias + exact GELU -> H   [MTOT, F]
    k_gemm<1><<<dim3(F / 128, MTOT / 128), 256>>>(x, weff_fc, b_fc, H, MTOT, F, D);
    // GEMM2 + bias -> out              [MTOT, D]
    k_gemm<0><<<dim3(D / 128, MTOT / 128), 256>>>(H, weff_proj, b_proj, out, MTOT, D, F);
}

// round 4
// speedup vs baseline: 2.1414x; 2.1414x over previous
#include <cuda_runtime.h>
#include <cuda_bf16.h>
#include <math.h>
#include <stdint.h>

#define D 1024
#define F 4096
#define MTOT 8192

typedef __nv_bfloat16 bf16;

// ---- scratch (static device globals: allocation-free) ----
__device__ bf16 g_xh[(size_t)MTOT * D];   // 16 MB
__device__ bf16 g_xl[(size_t)MTOT * D];
__device__ bf16 g_wfch[(size_t)F * D];    // 8 MB
__device__ bf16 g_wfcl[(size_t)F * D];
__device__ bf16 g_hh[(size_t)MTOT * F];   // 64 MB
__device__ bf16 g_hl[(size_t)MTOT * F];
__device__ bf16 g_wph[(size_t)D * F];     // 8 MB
__device__ bf16 g_wpl[(size_t)D * F];
__device__ unsigned int g_max2[2];

// ===========================================================================
// helpers
// ===========================================================================
__device__ __forceinline__ uint32_t smem_u32(const void* p) {
    uint32_t a;
    asm("{ .reg .u64 t; cvta.to.shared.u64 t, %1; cvt.u32.u64 %0, t; }" : "=r"(a) : "l"(p));
    return a;
}
__device__ __forceinline__ void cp16(uint32_t s, const void* g) {
    asm volatile("cp.async.cg.shared.global [%0], [%1], 16;" :: "r"(s), "l"(g));
}
__device__ __forceinline__ void cp_commit() {
    asm volatile("cp.async.commit_group;");
}
__device__ __forceinline__ void cp_wait1() {
    asm volatile("cp.async.wait_group 1;");
}
__device__ __forceinline__ void ldsm4(uint32_t a, uint32_t& r0, uint32_t& r1,
                                      uint32_t& r2, uint32_t& r3) {
    asm volatile("ldmatrix.sync.aligned.m8n8.x4.shared.b16 {%0,%1,%2,%3}, [%4];"
                 : "=r"(r0), "=r"(r1), "=r"(r2), "=r"(r3) : "r"(a));
}
__device__ __forceinline__ void mma16816(float* c, const uint32_t* a, uint32_t b0, uint32_t b1) {
    asm volatile(
        "mma.sync.aligned.m16n8k16.row.col.f32.bf16.bf16.f32 "
        "{%0,%1,%2,%3}, {%4,%5,%6,%7}, {%8,%9}, {%0,%1,%2,%3};"
        : "+f"(c[0]), "+f"(c[1]), "+f"(c[2]), "+f"(c[3])
        : "r"(a[0]), "r"(a[1]), "r"(a[2]), "r"(a[3]), "r"(b0), "r"(b1));
}
__device__ __forceinline__ void split2(float v, bf16& h, bf16& l) {
    h = __float2bfloat16(v);
    l = __float2bfloat16(v - __bfloat162float(h));
}

// ===========================================================================
// pre-pass kernels
// ===========================================================================
__global__ void k_init_max() { g_max2[0] = 0u; g_max2[1] = 0u; }

__global__ void k_absmax(const float* __restrict__ W, int n, int sel) {
    float m = 0.f;
    int stride = gridDim.x * blockDim.x;
    for (int i = blockIdx.x * blockDim.x + threadIdx.x; i < n; i += stride)
        m = fmaxf(m, fabsf(W[i]));
    #pragma unroll
    for (int o = 16; o; o >>= 1) m = fmaxf(m, __shfl_xor_sync(0xffffffffu, m, o));
    __shared__ float sm[8];
    int lane = threadIdx.x & 31, w = threadIdx.x >> 5;
    if (lane == 0) sm[w] = m;
    __syncthreads();
    if (threadIdx.x == 0) {
        float mm = sm[0];
        for (int i = 1; i < 8; i++) mm = fmaxf(mm, sm[i]);
        atomicMax(&g_max2[sel], __float_as_uint(mm));
    }
}

// fakequant(W) + 2*B@A -> split bf16 h/l, plain row-major [out, K]
__global__ void k_split_w(const float* __restrict__ W, const float* __restrict__ A,
                          const float* __restrict__ Bm,
                          bf16* __restrict__ Wh, bf16* __restrict__ Wl,
                          int K, int sel) {
    int o = blockIdx.y;
    __shared__ float Bs[16];
    if (threadIdx.x < 16) Bs[threadIdx.x] = Bm[o * 16 + threadIdx.x];
    __syncthreads();
    float mx = __uint_as_float(g_max2[sel]);
    float scale = mx * (1.0f / 127.0f);
    float inv   = 127.0f / mx;
    int k = (blockIdx.x * blockDim.x + threadIdx.x) * 2;
    float w0 = W[(size_t)o * K + k], w1 = W[(size_t)o * K + k + 1];
    float q0 = fminf(fmaxf(rintf(w0 * inv), -128.f), 127.f) * scale;
    float q1 = fminf(fmaxf(rintf(w1 * inv), -128.f), 127.f) * scale;
    float a0 = 0.f, a1 = 0.f;
    #pragma unroll
    for (int r = 0; r < 16; r++) {
        a0 = fmaf(Bs[r], A[(size_t)r * K + k],     a0);
        a1 = fmaf(Bs[r], A[(size_t)r * K + k + 1], a1);
    }
    float v0 = q0 + 2.0f * a0, v1 = q1 + 2.0f * a1;
    bf16 h0, h1, l0, l1;
    split2(v0, h0, l0); split2(v1, h1, l1);
    *(__nv_bfloat162*)(Wh + (size_t)o * K + k) = __nv_bfloat162(h0, h1);
    *(__nv_bfloat162*)(Wl + (size_t)o * K + k) = __nv_bfloat162(l0, l1);
}

__global__ void k_split_x(const float4* __restrict__ x,
                          bf16* __restrict__ xh, bf16* __restrict__ xl) {
    size_t i = (size_t)blockIdx.x * blockDim.x + threadIdx.x;
    float4 v = x[i];
    bf16 h0, h1, h2, h3, l0, l1, l2, l3;
    split2(v.x, h0, l0); split2(v.y, h1, l1);
    split2(v.z, h2, l2); split2(v.w, h3, l3);
    __nv_bfloat162* ph = (__nv_bfloat162*)(xh + i * 4);
    __nv_bfloat162* pl = (__nv_bfloat162*)(xl + i * 4);
    ph[0] = __nv_bfloat162(h0, h1); ph[1] = __nv_bfloat162(h2, h3);
    pl[0] = __nv_bfloat162(l0, l1); pl[1] = __nv_bfloat162(l2, l3);
}

// ===========================================================================
// GEMM: C[M,N] = A[M,K] * B[N,K]^T + bias, error-compensated bf16 split
// CTA tile 128x128, BK=32, 3-stage cp.async pipeline, 8 warps x (64x32) tiles
// MODE 0: epilogue bias + exact GELU -> split h/l bf16 arrays (row-major)
// MODE 1: epilogue bias -> fp32 out
// ===========================================================================
#define BK 32
#define RSB 80                      // smem row stride bytes (64B data + 16B pad)
#define MAT_B (128 * RSB)           // 10240 per matrix
#define STAGE_B (4 * MAT_B)         // Ah, Al, Bh, Bl
#define GSMEM (3 * STAGE_B)         // 122880

template <int MODE>
__global__ void __launch_bounds__(256, 1)
k_gemm(const bf16* __restrict__ Ah, const bf16* __restrict__ Al,
       const bf16* __restrict__ Bh, const bf16* __restrict__ Bl,
       const float* __restrict__ bias, float* __restrict__ outf,
       bf16* __restrict__ outHh, bf16* __restrict__ outHl,
       int K, int N) {
    extern __shared__ char smem[];
    uint32_t sb = smem_u32(smem);
    int tid = threadIdx.x, wid = tid >> 5, lane = tid & 31;
    int m0 = blockIdx.y * 128;          // A rows
    int n0 = blockIdx.x * 128;          // B rows (= C cols)
    int warp_m = (wid >> 2) * 64;
    int warp_n = (wid & 3) * 32;

    // per-thread load mapping: 512 chunks of 16B per matrix, 2 per thread
    int r0i = tid >> 2;                 // rows: r0i and r0i+64
    int c0i = tid & 3;

    const bf16* gA[2] = { Ah, Al };
    const bf16* gB[2] = { Bh, Bl };

    // acc[mi][ni][4]
    float acc[4][4][4];
    #pragma unroll
    for (int i = 0; i < 4; i++)
        #pragma unroll
        for (int j = 0; j < 4; j++)
            #pragma unroll
            for (int q = 0; q < 4; q++) acc[i][j][q] = 0.f;

    int KT = K / BK;

    // ldmatrix per-lane base offsets (within a matrix)
    uint32_t a_off[4], b_off[2];
    #pragma unroll
    for (int mi = 0; mi < 4; mi++)
        a_off[mi] = (uint32_t)((warp_m + mi * 16 + (lane & 15)) * RSB + (lane >> 4) * 16);
    #pragma unroll
    for (int g = 0; g < 2; g++)
        b_off[g] = (uint32_t)((warp_n + g * 16 + (lane & 15)) * RSB + (lane >> 4) * 16);

    // stage loader
    auto load_stage = [&](int slot, int kt) {
        uint32_t st = sb + slot * STAGE_B;
        int kb = kt * BK;
        #pragma unroll
        for (int h = 0; h < 2; h++) {       // h=0: high, h=1: low
            #pragma unroll
            for (int j = 0; j < 2; j++) {
                int row = r0i + j * 64;
                uint32_t s_off = (uint32_t)(row * RSB + c0i * 16);
                // A matrix (h: 0 or 1)
                cp16(st + h * MAT_B + s_off,
                     gA[h] + (size_t)(m0 + row) * K + kb + c0i * 8);
                // B matrix
                cp16(st + (2 + h) * MAT_B + s_off,
                     gB[h] + (size_t)(n0 + row) * K + kb + c0i * 8);
            }
        }
        cp_commit();
    };

    load_stage(0, 0);
    load_stage(1, 1);

    for (int kt = 0; kt < KT; kt++) {
        cp_wait1();
        __syncthreads();
        if (kt + 2 < KT) load_stage((kt + 2) % 3, kt + 2);

        uint32_t st = sb + (kt % 3) * STAGE_B;
        #pragma unroll
        for (int s = 0; s < 2; s++) {       // two k16 sub-steps
            uint32_t ks = s * 32;           // byte offset within row
            uint32_t ah[4][4], al[4][4], bh[2][4], bl[2][4];
            #pragma unroll
            for (int mi = 0; mi < 4; mi++) {
                ldsm4(st + a_off[mi] + ks, ah[mi][0], ah[mi][1], ah[mi][2], ah[mi][3]);
                ldsm4(st + MAT_B + a_off[mi] + ks, al[mi][0], al[mi][1], al[mi][2], al[mi][3]);
            }
            #pragma unroll
            for (int g = 0; g < 2; g++) {
                ldsm4(st + 2 * MAT_B + b_off[g] + ks, bh[g][0], bh[g][1], bh[g][2], bh[g][3]);
                ldsm4(st + 3 * MAT_B + b_off[g] + ks, bl[g][0], bl[g][1], bl[g][2], bl[g][3]);
            }
            #pragma unroll
            for (int mi = 0; mi < 4; mi++) {
                #pragma unroll
                for (int ni = 0; ni < 4; ni++) {
                    int g = ni >> 1, sel = ni & 1;
                    uint32_t b0h = bh[g][sel], b1h = bh[g][sel + 2];
                    uint32_t b0l = bl[g][sel], b1l = bl[g][sel + 2];
                    mma16816(acc[mi][ni], ah[mi], b0h, b1h);   // Ah*Bh
                    mma16816(acc[mi][ni], al[mi], b0h, b1h);   // Al*Bh
                    mma16816(acc[mi][ni], ah[mi], b0l, b1l);   // Ah*Bl
                }
            }
        }
        __syncthreads();
    }

    // ---- epilogue ----
    int gid = lane >> 2, tig = lane & 3;
    #pragma unroll
    for (int mi = 0; mi < 4; mi++) {
        int row = m0 + warp_m + mi * 16 + gid;
        #pragma unroll
        for (int ni = 0; ni < 4; ni++) {
            int col = n0 + warp_n + ni * 8 + tig * 2;
            float bcol0 = __ldg(&bias[col]), bcol1 = __ldg(&bias[col + 1]);
            #pragma unroll
            for (int half = 0; half < 2; half++) {   // c0,c1 then c2,c3 (row+8)
                int rr = row + half * 8;
                float v0 = acc[mi][ni][half * 2 + 0] + bcol0;
                float v1 = acc[mi][ni][half * 2 + 1] + bcol1;
                if (MODE == 0) {
                    v0 = 0.5f * v0 * (1.0f + erff(v0 * 0.70710678118654752f));
                    v1 = 0.5f * v1 * (1.0f + erff(v1 * 0.70710678118654752f));
                    bf16 h0, h1, l0, l1;
                    split2(v0, h0, l0); split2(v1, h1, l1);
                    *(__nv_bfloat162*)(outHh + (size_t)rr * N + col) = __nv_bfloat162(h0, h1);
                    *(__nv_bfloat162*)(outHl + (size_t)rr * N + col) = __nv_bfloat162(l0, l1);
                } else {
                    float2 v; v.x = v0; v.y = v1;
                    *(float2*)(outf + (size_t)rr * N + col) = v;
                }
            }
        }
    }
}

// ===========================================================================
extern "C" void kernel_launch(void* const* d_in, const int* in_sizes, int n_in,
                              void* d_out, int out_size) {
    const float* x      = (const float*)d_in[0];
    const float* W_fc   = (const float*)d_in[1];
    const float* b_fc   = (const float*)d_in[2];
    const float* A_fc   = (const float*)d_in[3];
    const float* B_fc   = (const float*)d_in[4];
    const float* W_proj = (const float*)d_in[5];
    const float* b_proj = (const float*)d_in[6];
    const float* A_proj = (const float*)d_in[7];
    const float* B_proj = (const float*)d_in[8];
    float* out = (float*)d_out;

    bf16 *xh, *xl, *wfch, *wfcl, *hh, *hl, *wph, *wpl;
    cudaGetSymbolAddress((void**)&xh,   g_xh);
    cudaGetSymbolAddress((void**)&xl,   g_xl);
    cudaGetSymbolAddress((void**)&wfch, g_wfch);
    cudaGetSymbolAddress((void**)&wfcl, g_wfcl);
    cudaGetSymbolAddress((void**)&hh,   g_hh);
    cudaGetSymbolAddress((void**)&hl,   g_hl);
    cudaGetSymbolAddress((void**)&wph,  g_wph);
    cudaGetSymbolAddress((void**)&wpl,  g_wpl);

    cudaFuncSetAttribute(k_gemm<0>, cudaFuncAttributeMaxDynamicSharedMemorySize, GSMEM);
    cudaFuncSetAttribute(k_gemm<1>, cudaFuncAttributeMaxDynamicSharedMemorySize, GSMEM);

    k_init_max<<<1, 32>>>();
    k_absmax<<<256, 256>>>(W_fc,   F * D, 0);
    k_absmax<<<256, 256>>>(W_proj, D * F, 1);

    k_split_w<<<dim3(D / 512, F), 256>>>(W_fc,   A_fc,   B_fc,   wfch, wfcl, D, 0);
    k_split_w<<<dim3(F / 512, D), 256>>>(W_proj, A_proj, B_proj, wph,  wpl,  F, 1);
    k_split_x<<<(MTOT * D / 4) / 256, 256>>>((const float4*)x, xh, xl);

    // GEMM1: [8192,1024] x [4096,1024]^T -> GELU -> split H
    k_gemm<0><<<dim3(F / 128, MTOT / 128), 256, GSMEM>>>(
        xh, xl, wfch, wfcl, b_fc, nullptr, hh, hl, D, F);
    // GEMM2: [8192,4096] x [1024,4096]^T -> fp32 out
    k_gemm<1><<<dim3(D / 128, MTOT / 128), 256, GSMEM>>>(
        hh, hl, wph, wpl, b_proj, out, nullptr, nullptr, F, D);
}

// round 5
// speedup vs baseline: 2.8962x; 1.3525x over previous
#include <cuda_runtime.h>
#include <cuda_fp16.h>
#include <math.h>
#include <stdint.h>

#define D 1024
#define F 4096
#define MTOT 8192

typedef __half fp16;

// ---- scratch (static device globals: allocation-free) ----
__device__ fp16 g_xh[(size_t)MTOT * D];   // 16 MB
__device__ fp16 g_xl[(size_t)MTOT * D];
__device__ fp16 g_wfc[(size_t)F * D];     // 8 MB  (single fp16)
__device__ fp16 g_hh[(size_t)MTOT * F];   // 64 MB
__device__ fp16 g_hl[(size_t)MTOT * F];
__device__ fp16 g_wp[(size_t)D * F];      // 8 MB  (single fp16)
__device__ unsigned int g_max2[2];

// ===========================================================================
// helpers
// ===========================================================================
__device__ __forceinline__ uint32_t smem_u32(const void* p) {
    uint32_t a;
    asm("{ .reg .u64 t; cvta.to.shared.u64 t, %1; cvt.u32.u64 %0, t; }" : "=r"(a) : "l"(p));
    return a;
}
__device__ __forceinline__ void cp16(uint32_t s, const void* g) {
    asm volatile("cp.async.cg.shared.global [%0], [%1], 16;" :: "r"(s), "l"(g));
}
__device__ __forceinline__ void cp_commit() {
    asm volatile("cp.async.commit_group;");
}
__device__ __forceinline__ void cp_wait2() {
    asm volatile("cp.async.wait_group 2;");
}
__device__ __forceinline__ void ldsm4(uint32_t a, uint32_t& r0, uint32_t& r1,
                                      uint32_t& r2, uint32_t& r3) {
    asm volatile("ldmatrix.sync.aligned.m8n8.x4.shared.b16 {%0,%1,%2,%3}, [%4];"
                 : "=r"(r0), "=r"(r1), "=r"(r2), "=r"(r3) : "r"(a));
}
__device__ __forceinline__ void mma16816(float* c, const uint32_t* a, uint32_t b0, uint32_t b1) {
    asm volatile(
        "mma.sync.aligned.m16n8k16.row.col.f32.f16.f16.f32 "
        "{%0,%1,%2,%3}, {%4,%5,%6,%7}, {%8,%9}, {%0,%1,%2,%3};"
        : "+f"(c[0]), "+f"(c[1]), "+f"(c[2]), "+f"(c[3])
        : "r"(a[0]), "r"(a[1]), "r"(a[2]), "r"(a[3]), "r"(b0), "r"(b1));
}
__device__ __forceinline__ void split2(float v, fp16& h, fp16& l) {
    h = __float2half(v);
    l = __float2half(v - __half2float(h));
}

// ===========================================================================
// pre-pass kernels
// ===========================================================================
__global__ void k_init_max() { g_max2[0] = 0u; g_max2[1] = 0u; }

__global__ void k_absmax(const float* __restrict__ W, int n, int sel) {
    float m = 0.f;
    int stride = gridDim.x * blockDim.x;
    for (int i = blockIdx.x * blockDim.x + threadIdx.x; i < n; i += stride)
        m = fmaxf(m, fabsf(W[i]));
    #pragma unroll
    for (int o = 16; o; o >>= 1) m = fmaxf(m, __shfl_xor_sync(0xffffffffu, m, o));
    __shared__ float sm[8];
    int lane = threadIdx.x & 31, w = threadIdx.x >> 5;
    if (lane == 0) sm[w] = m;
    __syncthreads();
    if (threadIdx.x == 0) {
        float mm = sm[0];
        for (int i = 1; i < 8; i++) mm = fmaxf(mm, sm[i]);
        atomicMax(&g_max2[sel], __float_as_uint(mm));
    }
}

// fakequant(W) + 2*B@A -> single fp16, row-major [out, K]
__global__ void k_quant_w(const float* __restrict__ W, const float* __restrict__ A,
                          const float* __restrict__ Bm, fp16* __restrict__ Wo,
                          int K, int sel) {
    int o = blockIdx.y;
    __shared__ float Bs[16];
    if (threadIdx.x < 16) Bs[threadIdx.x] = Bm[o * 16 + threadIdx.x];
    __syncthreads();
    float mx = __uint_as_float(g_max2[sel]);
    float scale = mx * (1.0f / 127.0f);
    float inv   = 127.0f / mx;
    int k = (blockIdx.x * blockDim.x + threadIdx.x) * 2;
    float w0 = W[(size_t)o * K + k], w1 = W[(size_t)o * K + k + 1];
    float q0 = fminf(fmaxf(rintf(w0 * inv), -128.f), 127.f) * scale;
    float q1 = fminf(fmaxf(rintf(w1 * inv), -128.f), 127.f) * scale;
    float a0 = 0.f, a1 = 0.f;
    #pragma unroll
    for (int r = 0; r < 16; r++) {
        a0 = fmaf(Bs[r], A[(size_t)r * K + k],     a0);
        a1 = fmaf(Bs[r], A[(size_t)r * K + k + 1], a1);
    }
    float v0 = q0 + 2.0f * a0, v1 = q1 + 2.0f * a1;
    *(__half2*)(Wo + (size_t)o * K + k) = __floats2half2_rn(v0, v1);
}

__global__ void k_split_x(const float4* __restrict__ x,
                          fp16* __restrict__ xh, fp16* __restrict__ xl) {
    size_t i = (size_t)blockIdx.x * blockDim.x + threadIdx.x;
    float4 v = x[i];
    fp16 h0, h1, h2, h3, l0, l1, l2, l3;
    split2(v.x, h0, l0); split2(v.y, h1, l1);
    split2(v.z, h2, l2); split2(v.w, h3, l3);
    __half2* ph = (__half2*)(xh + i * 4);
    __half2* pl = (__half2*)(xl + i * 4);
    ph[0] = __halves2half2(h0, h1); ph[1] = __halves2half2(h2, h3);
    pl[0] = __halves2half2(l0, l1); pl[1] = __halves2half2(l2, l3);
}

// ===========================================================================
// GEMM: C[M,N] = A[M,K] * B[N,K]^T + bias, fp16 2-term compensated
// CTA 128x128, BK=32, 4-stage cp.async pipeline, 8 warps x (64x32)
// MODE 0: epilogue bias + exact GELU -> split h/l fp16 (row-major)
// MODE 1: epilogue bias -> fp32 out
// ===========================================================================
#define BK 32
#define RSB 80                       // smem row stride bytes (64B data + 16B pad)
#define MAT_B (128 * RSB)            // 10240 per matrix
#define STAGE_B (3 * MAT_B)          // Ah, Al, B
#define NSTAGE 4
#define GSMEM (NSTAGE * STAGE_B)     // 122880

template <int MODE>
__global__ void __launch_bounds__(256, 1)
k_gemm(const fp16* __restrict__ Ah, const fp16* __restrict__ Al,
       const fp16* __restrict__ Bw,
       const float* __restrict__ bias, float* __restrict__ outf,
       fp16* __restrict__ outHh, fp16* __restrict__ outHl,
       int K, int N) {
    extern __shared__ char smem[];
    uint32_t sb = smem_u32(smem);
    int tid = threadIdx.x, wid = tid >> 5, lane = tid & 31;
    int m0 = blockIdx.y * 128;
    int n0 = blockIdx.x * 128;
    int warp_m = (wid >> 2) * 64;
    int warp_n = (wid & 3) * 32;

    int r0i = tid >> 2;              // rows r0i, r0i+64
    int c0i = tid & 3;               // 16B chunk within 64B row

    float acc[4][4][4];
    #pragma unroll
    for (int i = 0; i < 4; i++)
        #pragma unroll
        for (int j = 0; j < 4; j++)
            #pragma unroll
            for (int q = 0; q < 4; q++) acc[i][j][q] = 0.f;

    int KT = K / BK;

    uint32_t a_off[4], b_off[2];
    #pragma unroll
    for (int mi = 0; mi < 4; mi++)
        a_off[mi] = (uint32_t)((warp_m + mi * 16 + (lane & 15)) * RSB + (lane >> 4) * 16);
    #pragma unroll
    for (int g = 0; g < 2; g++)
        b_off[g] = (uint32_t)((warp_n + g * 16 + (lane & 15)) * RSB + (lane >> 4) * 16);

    auto load_stage = [&](int slot, int kt) {
        uint32_t st = sb + slot * STAGE_B;
        int kb = kt * BK;
        #pragma unroll
        for (int j = 0; j < 2; j++) {
            int row = r0i + j * 64;
            uint32_t s_off = (uint32_t)(row * RSB + c0i * 16);
            const fp16* gcol;
            gcol = Ah + (size_t)(m0 + row) * K + kb + c0i * 8;
            cp16(st + s_off, gcol);
            gcol = Al + (size_t)(m0 + row) * K + kb + c0i * 8;
            cp16(st + MAT_B + s_off, gcol);
            gcol = Bw + (size_t)(n0 + row) * K + kb + c0i * 8;
            cp16(st + 2 * MAT_B + s_off, gcol);
        }
        cp_commit();
    };

    load_stage(0, 0);
    load_stage(1, 1);
    load_stage(2, 2);

    for (int kt = 0; kt < KT; kt++) {
        cp_wait2();
        __syncthreads();
        if (kt + 3 < KT) load_stage((kt + 3) % NSTAGE, kt + 3);

        uint32_t st = sb + (kt % NSTAGE) * STAGE_B;
        #pragma unroll
        for (int s = 0; s < 2; s++) {
            uint32_t ks = s * 32;
            uint32_t ah[4][4], al[4][4], bf[2][4];
            #pragma unroll
            for (int g = 0; g < 2; g++)
                ldsm4(st + 2 * MAT_B + b_off[g] + ks, bf[g][0], bf[g][1], bf[g][2], bf[g][3]);
            #pragma unroll
            for (int mi = 0; mi < 4; mi++) {
                ldsm4(st + a_off[mi] + ks,         ah[mi][0], ah[mi][1], ah[mi][2], ah[mi][3]);
                ldsm4(st + MAT_B + a_off[mi] + ks, al[mi][0], al[mi][1], al[mi][2], al[mi][3]);
            }
            #pragma unroll
            for (int mi = 0; mi < 4; mi++) {
                #pragma unroll
                for (int ni = 0; ni < 4; ni++) {
                    int g = ni >> 1, sel = ni & 1;
                    uint32_t b0 = bf[g][sel], b1 = bf[g][sel + 2];
                    mma16816(acc[mi][ni], ah[mi], b0, b1);   // Ah*B
                    mma16816(acc[mi][ni], al[mi], b0, b1);   // Al*B
                }
            }
        }
        __syncthreads();
    }

    // ---- epilogue ----
    int gid = lane >> 2, tig = lane & 3;
    #pragma unroll
    for (int mi = 0; mi < 4; mi++) {
        int row = m0 + warp_m + mi * 16 + gid;
        #pragma unroll
        for (int ni = 0; ni < 4; ni++) {
            int col = n0 + warp_n + ni * 8 + tig * 2;
            float bcol0 = __ldg(&bias[col]), bcol1 = __ldg(&bias[col + 1]);
            #pragma unroll
            for (int half = 0; half < 2; half++) {
                int rr = row + half * 8;
                float v0 = acc[mi][ni][half * 2 + 0] + bcol0;
                float v1 = acc[mi][ni][half * 2 + 1] + bcol1;
                if (MODE == 0) {
                    v0 = 0.5f * v0 * (1.0f + erff(v0 * 0.70710678118654752f));
                    v1 = 0.5f * v1 * (1.0f + erff(v1 * 0.70710678118654752f));
                    fp16 h0, h1, l0, l1;
                    split2(v0, h0, l0); split2(v1, h1, l1);
                    *(__half2*)(outHh + (size_t)rr * N + col) = __halves2half2(h0, h1);
                    *(__half2*)(outHl + (size_t)rr * N + col) = __halves2half2(l0, l1);
                } else {
                    float2 v; v.x = v0; v.y = v1;
                    *(float2*)(outf + (size_t)rr * N + col) = v;
                }
            }
        }
    }
}

// ===========================================================================
extern "C" void kernel_launch(void* const* d_in, const int* in_sizes, int n_in,
                              void* d_out, int out_size) {
    const float* x      = (const float*)d_in[0];
    const float* W_fc   = (const float*)d_in[1];
    const float* b_fc   = (const float*)d_in[2];
    const float* A_fc   = (const float*)d_in[3];
    const float* B_fc   = (const float*)d_in[4];
    const float* W_proj = (const float*)d_in[5];
    const float* b_proj = (const float*)d_in[6];
    const float* A_proj = (const float*)d_in[7];
    const float* B_proj = (const float*)d_in[8];
    float* out = (float*)d_out;

    fp16 *xh, *xl, *wfc, *hh, *hl, *wp;
    cudaGetSymbolAddress((void**)&xh,  g_xh);
    cudaGetSymbolAddress((void**)&xl,  g_xl);
    cudaGetSymbolAddress((void**)&wfc, g_wfc);
    cudaGetSymbolAddress((void**)&hh,  g_hh);
    cudaGetSymbolAddress((void**)&hl,  g_hl);
    cudaGetSymbolAddress((void**)&wp,  g_wp);

    cudaFuncSetAttribute(k_gemm<0>, cudaFuncAttributeMaxDynamicSharedMemorySize, GSMEM);
    cudaFuncSetAttribute(k_gemm<1>, cudaFuncAttributeMaxDynamicSharedMemorySize, GSMEM);

    k_init_max<<<1, 32>>>();
    k_absmax<<<256, 256>>>(W_fc,   F * D, 0);
    k_absmax<<<256, 256>>>(W_proj, D * F, 1);

    k_quant_w<<<dim3(D / 512, F), 256>>>(W_fc,   A_fc,   B_fc,   wfc, D, 0);
    k_quant_w<<<dim3(F / 512, D), 256>>>(W_proj, A_proj, B_proj, wp,  F, 1);
    k_split_x<<<(MTOT * D / 4) / 256, 256>>>((const float4*)x, xh, xl);

    // GEMM1: [8192,1024] x [4096,1024]^T -> GELU -> split H
    k_gemm<0><<<dim3(F / 128, MTOT / 128), 256, GSMEM>>>(
        xh, xl, wfc, b_fc, nullptr, hh, hl, D, F);
    // GEMM2: [8192,4096] x [1024,4096]^T -> fp32 out
    k_gemm<1><<<dim3(D / 128, MTOT / 128), 256, GSMEM>>>(
        hh, hl, wp, b_proj, out, nullptr, nullptr, F, D);
}

// round 8
// speedup vs baseline: 5.4123x; 1.8688x over previous
#include <cuda_runtime.h>
#include <cuda_fp16.h>
#include <math.h>
#include <stdint.h>

#define D 1024
#define F 4096
#define MTOT 8192

typedef __half fp16;

// ---- scratch (static device globals: allocation-free) ----
__device__ fp16 g_x16[(size_t)MTOT * D];  // 16 MB
__device__ fp16 g_wfc[(size_t)F * D];     // 8 MB
__device__ fp16 g_h16[(size_t)MTOT * F];  // 64 MB
__device__ fp16 g_wp[(size_t)D * F];      // 8 MB
__device__ unsigned int g_max2[2];

// ===========================================================================
// helpers
// ===========================================================================
__device__ __forceinline__ uint32_t smem_u32(const void* p) {
    uint32_t a;
    asm("{ .reg .u64 t; cvta.to.shared.u64 t, %1; cvt.u32.u64 %0, t; }" : "=r"(a) : "l"(p));
    return a;
}
__device__ __forceinline__ void cp16(uint32_t s, const void* g) {
    asm volatile("cp.async.cg.shared.global [%0], [%1], 16;" :: "r"(s), "l"(g));
}
__device__ __forceinline__ void cp_commit() {
    asm volatile("cp.async.commit_group;");
}
__device__ __forceinline__ void cp_wait2() {
    asm volatile("cp.async.wait_group 2;");
}
__device__ __forceinline__ void ldsm4(uint32_t a, uint32_t& r0, uint32_t& r1,
                                      uint32_t& r2, uint32_t& r3) {
    asm volatile("ldmatrix.sync.aligned.m8n8.x4.shared.b16 {%0,%1,%2,%3}, [%4];"
                 : "=r"(r0), "=r"(r1), "=r"(r2), "=r"(r3) : "r"(a));
}
__device__ __forceinline__ void mma16816(float* c, const uint32_t* a, uint32_t b0, uint32_t b1) {
    asm volatile(
        "mma.sync.aligned.m16n8k16.row.col.f32.f16.f16.f32 "
        "{%0,%1,%2,%3}, {%4,%5,%6,%7}, {%8,%9}, {%0,%1,%2,%3};"
        : "+f"(c[0]), "+f"(c[1]), "+f"(c[2]), "+f"(c[3])
        : "r"(a[0]), "r"(a[1]), "r"(a[2]), "r"(a[3]), "r"(b0), "r"(b1));
}

// ===========================================================================
// pre-pass kernels
// ===========================================================================
__global__ void k_init_max() { g_max2[0] = 0u; g_max2[1] = 0u; }

__global__ void k_absmax(const float* __restrict__ W, int n, int sel) {
    float m = 0.f;
    int stride = gridDim.x * blockDim.x;
    for (int i = blockIdx.x * blockDim.x + threadIdx.x; i < n; i += stride)
        m = fmaxf(m, fabsf(W[i]));
    #pragma unroll
    for (int o = 16; o; o >>= 1) m = fmaxf(m, __shfl_xor_sync(0xffffffffu, m, o));
    __shared__ float sm[8];
    int lane = threadIdx.x & 31, w = threadIdx.x >> 5;
    if (lane == 0) sm[w] = m;
    __syncthreads();
    if (threadIdx.x == 0) {
        float mm = sm[0];
        for (int i = 1; i < 8; i++) mm = fmaxf(mm, sm[i]);
        atomicMax(&g_max2[sel], __float_as_uint(mm));
    }
}

// fakequant(W) + 2*B@A -> single fp16, row-major [out, K]
__global__ void k_quant_w(const float* __restrict__ W, const float* __restrict__ A,
                          const float* __restrict__ Bm, fp16* __restrict__ Wo,
                          int K, int sel) {
    int o = blockIdx.y;
    __shared__ float Bs[16];
    if (threadIdx.x < 16) Bs[threadIdx.x] = Bm[o * 16 + threadIdx.x];
    __syncthreads();
    float mx = __uint_as_float(g_max2[sel]);
    float scale = mx * (1.0f / 127.0f);
    float inv   = 127.0f / mx;
    int k = (blockIdx.x * blockDim.x + threadIdx.x) * 2;
    float w0 = W[(size_t)o * K + k], w1 = W[(size_t)o * K + k + 1];
    float q0 = fminf(fmaxf(rintf(w0 * inv), -128.f), 127.f) * scale;
    float q1 = fminf(fmaxf(rintf(w1 * inv), -128.f), 127.f) * scale;
    float a0 = 0.f, a1 = 0.f;
    #pragma unroll
    for (int r = 0; r < 16; r++) {
        a0 = fmaf(Bs[r], A[(size_t)r * K + k],     a0);
        a1 = fmaf(Bs[r], A[(size_t)r * K + k + 1], a1);
    }
    float v0 = q0 + 2.0f * a0, v1 = q1 + 2.0f * a1;
    *(__half2*)(Wo + (size_t)o * K + k) = __floats2half2_rn(v0, v1);
}

__global__ void k_convert_x(const float4* __restrict__ x, fp16* __restrict__ xo) {
    size_t i = (size_t)blockIdx.x * blockDim.x + threadIdx.x;
    float4 v = x[i];
    __half2* p = (__half2*)(xo + i * 4);
    p[0] = __floats2half2_rn(v.x, v.y);
    p[1] = __floats2half2_rn(v.z, v.w);
}

// ===========================================================================
// GEMM: C[M,N] = A[M,K] * B[N,K]^T + bias, pure fp16, fp32 accum
// CTA tile 128x256, BK=32, 4-stage cp.async pipeline
// 8 warps = 2(m) x 4(n), warp tile 64x64
// MODE 0: epilogue bias + exact GELU -> fp16 H (row-major)
// MODE 1: epilogue bias -> fp32 out
// ===========================================================================
#define BK 32
#define RSB 80                        // 64B data + 16B pad
#define MAT_A (128 * RSB)             // 10240
#define MAT_Bm (256 * RSB)            // 20480
#define STAGE_B (MAT_A + MAT_Bm)      // 30720
#define NSTAGE 4
#define GSMEM (NSTAGE * STAGE_B)      // 122880

template <int MODE>
__global__ void __launch_bounds__(256, 1)
k_gemm(const fp16* __restrict__ Ax, const fp16* __restrict__ Bw,
       const float* __restrict__ bias, float* __restrict__ outf,
       fp16* __restrict__ outH, int K, int N) {
    extern __shared__ char smem[];
    uint32_t sb = smem_u32(smem);
    int tid = threadIdx.x, wid = tid >> 5, lane = tid & 31;
    int m0 = blockIdx.y * 128;
    int n0 = blockIdx.x * 256;
    int warp_m = (wid >> 2) * 64;
    int warp_n = (wid & 3) * 64;

    int r0i = tid >> 2;               // base row 0..63
    int c0i = tid & 3;                // 16B chunk within 64B row

    float acc[4][8][4];
    #pragma unroll
    for (int i = 0; i < 4; i++)
        #pragma unroll
        for (int j = 0; j < 8; j++)
            #pragma unroll
            for (int q = 0; q < 4; q++) acc[i][j][q] = 0.f;

    int KT = K / BK;

    uint32_t a_off[4], b_off[4];
    #pragma unroll
    for (int mi = 0; mi < 4; mi++)
        a_off[mi] = (uint32_t)((warp_m + mi * 16 + (lane & 15)) * RSB + (lane >> 4) * 16);
    #pragma unroll
    for (int g = 0; g < 4; g++)
        b_off[g] = (uint32_t)(MAT_A + (warp_n + g * 16 + (lane & 15)) * RSB + (lane >> 4) * 16);

    auto load_stage = [&](int slot, int kt) {
        uint32_t st = sb + slot * STAGE_B;
        int kb = kt * BK;
        #pragma unroll
        for (int j = 0; j < 2; j++) {          // A: 128 rows
            int row = r0i + j * 64;
            cp16(st + (uint32_t)(row * RSB + c0i * 16),
                 Ax + (size_t)(m0 + row) * K + kb + c0i * 8);
        }
        #pragma unroll
        for (int j = 0; j < 4; j++) {          // B: 256 rows
            int row = r0i + j * 64;
            cp16(st + (uint32_t)(MAT_A + row * RSB + c0i * 16),
                 Bw + (size_t)(n0 + row) * K + kb + c0i * 8);
        }
        cp_commit();
    };

    load_stage(0, 0);
    load_stage(1, 1);
    load_stage(2, 2);

    for (int kt = 0; kt < KT; kt++) {
        cp_wait2();
        __syncthreads();
        if (kt + 3 < KT) load_stage((kt + 3) % NSTAGE, kt + 3);

        uint32_t st = sb + (kt % NSTAGE) * STAGE_B;
        #pragma unroll
        for (int s = 0; s < 2; s++) {
            uint32_t ks = s * 32;
            uint32_t af[4][4], bf[4][4];
            #pragma unroll
            for (int g = 0; g < 4; g++)
                ldsm4(st + b_off[g] + ks, bf[g][0], bf[g][1], bf[g][2], bf[g][3]);
            #pragma unroll
            for (int mi = 0; mi < 4; mi++)
                ldsm4(st + a_off[mi] + ks, af[mi][0], af[mi][1], af[mi][2], af[mi][3]);
            #pragma unroll
            for (int mi = 0; mi < 4; mi++) {
                #pragma unroll
                for (int ni = 0; ni < 8; ni++) {
                    int g = ni >> 1, sel = ni & 1;
                    mma16816(acc[mi][ni], af[mi], bf[g][sel], bf[g][sel + 2]);
                }
            }
        }
        __syncthreads();
    }

    // ---- epilogue ----
    int gid = lane >> 2, tig = lane & 3;
    #pragma unroll
    for (int mi = 0; mi < 4; mi++) {
        int row = m0 + warp_m + mi * 16 + gid;
        #pragma unroll
        for (int ni = 0; ni < 8; ni++) {
            int col = n0 + warp_n + ni * 8 + tig * 2;
            float bcol0 = __ldg(&bias[col]), bcol1 = __ldg(&bias[col + 1]);
            #pragma unroll
            for (int half = 0; half < 2; half++) {
                int rr = row + half * 8;
                float v0 = acc[mi][ni][half * 2 + 0] + bcol0;
                float v1 = acc[mi][ni][half * 2 + 1] + bcol1;
                if (MODE == 0) {
                    v0 = 0.5f * v0 * (1.0f + erff(v0 * 0.70710678118654752f));
                    v1 = 0.5f * v1 * (1.0f + erff(v1 * 0.70710678118654752f));
                    *(__half2*)(outH + (size_t)rr * N + col) = __floats2half2_rn(v0, v1);
                } else {
                    float2 v; v.x = v0; v.y = v1;
                    *(float2*)(outf + (size_t)rr * N + col) = v;
                }
            }
        }
    }
}

// ===========================================================================
extern "C" void kernel_launch(void* const* d_in, const int* in_sizes, int n_in,
                              void* d_out, int out_size) {
    const float* x      = (const float*)d_in[0];
    const float* W_fc   = (const float*)d_in[1];
    const float* b_fc   = (const float*)d_in[2];
    const float* A_fc   = (const float*)d_in[3];
    const float* B_fc   = (const float*)d_in[4];
    const float* W_proj = (const float*)d_in[5];
    const float* b_proj = (const float*)d_in[6];
    const float* A_proj = (const float*)d_in[7];
    const float* B_proj = (const float*)d_in[8];
    float* out = (float*)d_out;

    fp16 *x16, *wfc, *h16, *wp;
    cudaGetSymbolAddress((void**)&x16, g_x16);
    cudaGetSymbolAddress((void**)&wfc, g_wfc);
    cudaGetSymbolAddress((void**)&h16, g_h16);
    cudaGetSymbolAddress((void**)&wp,  g_wp);

    cudaFuncSetAttribute(k_gemm<0>, cudaFuncAttributeMaxDynamicSharedMemorySize, GSMEM);
    cudaFuncSetAttribute(k_gemm<1>, cudaFuncAttributeMaxDynamicSharedMemorySize, GSMEM);

    k_init_max<<<1, 32>>>();
    k_absmax<<<256, 256>>>(W_fc,   F * D, 0);
    k_absmax<<<256, 256>>>(W_proj, D * F, 1);

    k_quant_w<<<dim3(D / 512, F), 256>>>(W_fc,   A_fc,   B_fc,   wfc, D, 0);
    k_quant_w<<<dim3(F / 512, D), 256>>>(W_proj, A_proj, B_proj, wp,  F, 1);
    k_convert_x<<<(MTOT * D / 4) / 256, 256>>>((const float4*)x, x16);

    // GEMM1: [8192,1024] x [4096,1024]^T -> GELU -> fp16 H
    k_gemm<0><<<dim3(F / 256, MTOT / 128), 256, GSMEM>>>(
        x16, wfc, b_fc, nullptr, h16, D, F);
    // GEMM2: [8192,4096] x [1024,4096]^T -> fp32 out
    k_gemm<1><<<dim3(D / 256, MTOT / 128), 256, GSMEM>>>(
        h16, wp, b_proj, out, nullptr, F, D);
}